// round 17
// baseline (speedup 1.0000x reference)
#include <cuda_runtime.h>

// ParametricInterpolation — numerics FROZEN (bit-exact vs reference since R8):
//   p_k = RN(params_k * RN(1/fl32(scaler_k)))   (XLA divide->recip-mul)
//   i2 = RN(i*i), i3 = RN(i2*i), i4 = RN(i2*i2) (integer_pow sq-and-mul)
//   c  = RN(p0*i4); fma(p1,i3); fma(p2,i2); fma(p3,i); + p4  (ascending fma)
//   round-half-even (magic 2^23+2^22); k = RN(c - ci);
//   pos = clip(n - ci, 1, 2047)
//   out = RN(RN(x1*RN(1-k)) + RN(x2*k))          (non-contracted lerp)
//
// R17: TWO rows per CTA, lane-packed f32x2 — row A in lane-lo, row B in
// lane-hi of every packed op (each lane is an independent IEEE-RN fp32 op,
// bit-identical to the scalar chain; verified rel_err 0.0 in R16). One
// param-latency window covers 2 rows, 32 gather LDGs in flight per thread,
// half the CTA churn. Early gather issue + __stcs streaming stores kept.

#define SIG_LEN 2048
#define PARTS   8
#define MAGIC_F 12582912.0f       // 2^23 + 2^22
#define MAGIC_I 0x4B400000

typedef unsigned long long u64;

__device__ __forceinline__ u64 pack2(float lo, float hi) {
    u64 r; asm("mov.b64 %0, {%1, %2};" : "=l"(r) : "f"(lo), "f"(hi)); return r;
}
__device__ __forceinline__ void unpack2(u64 v, float& lo, float& hi) {
    asm("mov.b64 {%0, %1}, %2;" : "=f"(lo), "=f"(hi) : "l"(v));
}
__device__ __forceinline__ u64 mul2(u64 a, u64 b) {
    u64 d; asm("mul.rn.f32x2 %0, %1, %2;" : "=l"(d) : "l"(a), "l"(b)); return d;
}
__device__ __forceinline__ u64 add2(u64 a, u64 b) {
    u64 d; asm("add.rn.f32x2 %0, %1, %2;" : "=l"(d) : "l"(a), "l"(b)); return d;
}
__device__ __forceinline__ u64 fma2(u64 a, u64 b, u64 c) {
    u64 d; asm("fma.rn.f32x2 %0, %1, %2, %3;" : "=l"(d) : "l"(a), "l"(b), "l"(c)); return d;
}

__global__ __launch_bounds__(256, 4)
void pik_kernel(const float* __restrict__ x,
                const float* __restrict__ params,
                float* __restrict__ out)
{
    const int tid = threadIdx.x;
    const size_t rowA = (size_t)blockIdx.x * 2;   // rows 2b (lane lo), 2b+1 (lane hi)

    // Both rows' params: 10 independent warp-uniform LDGs, ONE latency window.
    const float* pa = params + rowA * 5;
    const float a0 = __ldg(pa + 0), a1 = __ldg(pa + 1), a2 = __ldg(pa + 2),
                a3 = __ldg(pa + 3), a4 = __ldg(pa + 4);
    const float b0 = __ldg(pa + 5), b1 = __ldg(pa + 6), b2 = __ldg(pa + 7),
                b3 = __ldg(pa + 8), b4 = __ldg(pa + 9);

    const float i12 = (float)(1.0 / (double)1e12f);
    const float i8  = (float)(1.0 / (double)1e8f);
    const float i4c = (float)(1.0 / (double)1e4f);
    const float i10 = (float)(1.0 / (double)10.0f);

    // lane-lo = row A, lane-hi = row B (per-lane RN mul == scalar frozen form)
    const u64 P0 = pack2(__fmul_rn(a0, i12), __fmul_rn(b0, i12));
    const u64 P1 = pack2(__fmul_rn(a1, i8),  __fmul_rn(b1, i8));
    const u64 P2 = pack2(__fmul_rn(a2, i4c), __fmul_rn(b2, i4c));
    const u64 P3 = pack2(a3, b3);            // inv = 1.0 exactly
    const u64 P4 = pack2(__fmul_rn(a4, i10), __fmul_rn(b4, i10));

    const u64 magic2 = pack2(MAGIC_F, MAGIC_F);
    const u64 nmag2  = pack2(-MAGIC_F, -MAGIC_F);
    const u64 none2  = pack2(-1.0f, -1.0f);

    const float* xA = x   + rowA * SIG_LEN;   // row B at +SIG_LEN (imm offset)
    float*       oA = out + rowA * SIG_LEN;

    const float fi0 = (float)tid;             // single I2F per thread

    u64   kk2[PARTS];                         // (kA, kB) per part
    float x1A[PARTS], x2A[PARTS], x1B[PARTS], x2B[PARTS];

    // Phase 1: packed curve (both rows) per part; gathers issue immediately.
    #pragma unroll
    for (int q = 0; q < PARTS; ++q) {
        const float fi = fi0 + (float)(q * 256);     // exact
        const u64 fi2 = pack2(fi, fi);

        const u64 i2 = mul2(fi2, fi2);               // exact per lane
        const u64 i3 = mul2(i2, fi2);
        const u64 i4 = mul2(i2, i2);

        u64 c = mul2(P0, i4);                        // ascending-k fma chain
        c = fma2(P1, i3, c);
        c = fma2(P2, i2, c);
        c = fma2(P3, fi2, c);
        c = add2(c, P4);

        const u64 y  = add2(c, magic2);              // round half to even
        const u64 ci = add2(y, nmag2);               // exact
        kk2[q] = fma2(ci, none2, c);                 // k = RN(c - ci)

        float ya, yb; unpack2(y, ya, yb);
        const int n   = q * 256 + tid;
        int pAi = n - (__float_as_int(ya) - MAGIC_I);
        int pBi = n - (__float_as_int(yb) - MAGIC_I);
        pAi = max(1, min(SIG_LEN - 1, pAi));
        pBi = max(1, min(SIG_LEN - 1, pBi));

        x1A[q] = __ldg(xA + pAi);                    // 4 LDGs per part in flight
        x2A[q] = __ldg(xA + pAi - 1);
        x1B[q] = __ldg(xA + SIG_LEN + pBi);
        x2B[q] = __ldg(xA + SIG_LEN + pBi - 1);
    }

    // Phase 2: unpack k, scalar non-contracted lerps, streaming stores.
    #pragma unroll
    for (int q = 0; q < PARTS; ++q) {
        float kA, kB; unpack2(kk2[q], kA, kB);
        const int n = q * 256 + tid;

        const float wA = __fsub_rn(1.0f, kA);
        const float vA = __fadd_rn(__fmul_rn(x1A[q], wA), __fmul_rn(x2A[q], kA));
        __stcs(oA + n, vA);

        const float wB = __fsub_rn(1.0f, kB);
        const float vB = __fadd_rn(__fmul_rn(x1B[q], wB), __fmul_rn(x2B[q], kB));
        __stcs(oA + SIG_LEN + n, vB);
    }
}

extern "C" void kernel_launch(void* const* d_in, const int* in_sizes, int n_in,
                              void* d_out, int out_size)
{
    const float* x;
    const float* params;
    if (n_in >= 2 && in_sizes[0] < in_sizes[1]) {
        params = (const float*)d_in[0];
        x      = (const float*)d_in[1];
    } else {
        x      = (const float*)d_in[0];
        params = (const float*)d_in[1];
    }
    float* out = (float*)d_out;

    const int batch = 16384;
    pik_kernel<<<batch / 2, 256>>>(x, params, out);
}